// round 12
// baseline (speedup 1.0000x reference)
#include <cuda_runtime.h>

#define MAXN 6016
#define NB   94                     // max number of 64-box blocks
#define TRI  (NB * (NB + 1) / 2)    // 4465 upper-triangle tiles
#define SPOOL 320                   // nonzero tiles preloaded into smem
typedef unsigned long long u64;

// Scratch (device globals: allocation is banned; zero-initialized at load)
__device__ float4 g_sboxes[MAXN];
__device__ int    g_rank[MAXN];
__device__ u64    g_plist[MAXN];        // packed (score_bits<<32)|idx
__device__ u64    g_pool[(size_t)TRI * 64];  // compacted nonzero tiles
__device__ int    g_slot[TRI];          // tile -> pool slot (-1 if zero tile)
__device__ u64    g_nzb[TRI];           // per-tile nonzero-row bitmaps
__device__ int    g_poolcnt;            // pool slots used; reset by scan
__device__ int    g_cnt;                // #prefix boxes; reset by scan

#define SCAN_THREADS 1024
// dynamic smem: pool | nzb | remv | keep | slot
#define SMEM_BYTES ((SPOOL * 64 + TRI + 2 * NB) * 8 + TRI * 4)

__device__ __forceinline__ int tri_start(int r) { return r * NB - (r * (r - 1)) / 2; }

__device__ __forceinline__ u64 redux_or64(u64 v) {
    unsigned lo = __reduce_or_sync(0xffffffffu, (unsigned)v);
    unsigned hi = __reduce_or_sync(0xffffffffu, (unsigned)(v >> 32));
    return (u64)lo | ((u64)hi << 32);
}

// ---------------------------------------------------------------------------
// 0) Compact prefix boxes (s >= 0.6) into g_plist.
// ---------------------------------------------------------------------------
__global__ void compact_kernel(const float* __restrict__ scores, int n) {
    int i = blockIdx.x * blockDim.x + threadIdx.x;
    if (i >= n) return;
    float s = scores[i];
    if (s >= 0.6f) {
        int p = atomicAdd(&g_cnt, 1);
        g_plist[p] = ((u64)__float_as_uint(s) << 32) | (unsigned)i;
    }
}

// ---------------------------------------------------------------------------
// 1) Rank within the prefix subset (== global rank for prefix boxes).
// ---------------------------------------------------------------------------
__global__ void rank_kernel(const float* __restrict__ boxes, int n) {
    const int w    = (blockIdx.x * blockDim.x + threadIdx.x) >> 5;
    const int lane = threadIdx.x & 31;
    const int m = g_cnt;
    if (w >= m) return;
    const u64 me = g_plist[w];
    const unsigned sb = (unsigned)(me >> 32);
    const unsigned ib = (unsigned)me;
    int cnt = 0;
    for (int j = lane; j < m; j += 32) {
        u64 e = g_plist[j];
        unsigned sj = (unsigned)(e >> 32);
        unsigned ij = (unsigned)e;
        cnt += (int)((sj > sb) | ((sj == sb) & (ij < ib)));
    }
    #pragma unroll
    for (int o = 16; o; o >>= 1) cnt += __shfl_down_sync(0xffffffffu, cnt, o);
    if (lane == 0) {
        g_sboxes[cnt] = ((const float4*)boxes)[ib];
        g_rank[ib]    = cnt;
    }
}

// ---------------------------------------------------------------------------
// 2) Suppression mask -> compact pool of NONZERO tiles + nzb bitmaps.
//    Slot order nondeterministic (atomicAdd) but data is read back through
//    g_slot, so kernel output is deterministic.
// ---------------------------------------------------------------------------
__global__ void mask_kernel(int n) {
    int m = g_cnt; if (m > n) m = n;
    const int mb = (m + 63) >> 6;

    // linear tile -> (rb, cb) with cb >= rb
    const int p = blockIdx.x;
    int rb = (int)((2.0f * NB + 1.0f
                    - sqrtf((2.0f * NB + 1.0f) * (2.0f * NB + 1.0f) - 8.0f * p)) * 0.5f);
    if (rb < 0) rb = 0;
    while (rb + 1 <= NB - 1 && tri_start(rb + 1) <= p) rb++;
    while (rb > 0 && tri_start(rb) > p) rb--;
    const int cb = rb + (p - tri_start(rb));
    if (rb >= mb || cb >= mb) return;

    const int t = threadIdx.x;                   // 0..63
    __shared__ float4   cbox[64];                // {cz, cw, -cx, -cy}
    __shared__ float    carea[64];
    __shared__ unsigned nzhalf[2];
    __shared__ int      slot_sh;
    const int col0 = cb * 64;
    if (col0 + t < m) {
        float4 c = g_sboxes[col0 + t];
        cbox[t]  = make_float4(c.z, c.w, -c.x, -c.y);
        carea[t] = (c.z - c.x) * (c.w - c.y);
    } else {
        cbox[t]  = make_float4(-1e30f, -1e30f, -1e30f, -1e30f);  // -> IoU 0
        carea[t] = 0.f;
    }
    __syncthreads();

    const int row = rb * 64 + t;
    const float4 b   = g_sboxes[row];            // stale if row>=m; bits forced 0
    const float  bz  = b.z,  bw  = b.w;
    const float  nbx = -b.x, nby = -b.y;
    const float  barea = (b.z - b.x) * (b.w - b.y);

    u64 bits = 0ULL;
    #pragma unroll
    for (int k = 0; k < 64; k++) {
        float4 c  = cbox[k];
        float iw  = fmaxf(fminf(bz, c.x) + fminf(nbx, c.z), 0.f);
        float ih  = fmaxf(fminf(bw, c.y) + fminf(nby, c.w), 0.f);
        float inter = iw * ih;
        float uni   = (barea + carea[k]) - inter;
        if (fmaf(-0.5f, uni, inter) > 0.f) bits |= (1ULL << k);
    }
    if (cb == rb) bits &= ((~1ULL) << t);        // keep only cols > row
    if (row >= m) bits = 0ULL;

    unsigned bal = __ballot_sync(0xffffffffu, bits != 0ULL);
    if ((t & 31) == 0) nzhalf[t >> 5] = bal;
    __syncthreads();
    if (t == 0) {
        u64 nzw = (u64)nzhalf[0] | ((u64)nzhalf[1] << 32);
        int s = (nzw != 0ULL) ? atomicAdd(&g_poolcnt, 1) : -1;
        g_nzb[p]  = nzw;
        g_slot[p] = s;
        slot_sh   = s;
    }
    __syncthreads();
    const int s = slot_sh;
    if (s >= 0) g_pool[(size_t)s * 64 + t] = bits;
}

// ---------------------------------------------------------------------------
// 3) Greedy scan + finalize. Full CTA preloads the entire (sparse) working
//    set into smem, then ONE WARP runs the whole greedy loop barrier-free:
//      - lanes pre-issue nzb tests for future columns (off the serial chain)
//      - lane 0 resolves block b (remv[b] is final: eager application)
//      - ballots find hit columns; per hit the warp gathers the smem tile,
//        redux.or, lane 0 ORs remv[j] (single writer, no atomics)
//    Only 2 CTA-wide barriers total (after preload, before finalize).
// ---------------------------------------------------------------------------
__global__ void scan_kernel(const float* __restrict__ scores,
                            float* __restrict__ out, int n) {
    extern __shared__ u64 dyn[];
    u64* pool_s = dyn;                       // SPOOL*64
    u64* nzb_s  = pool_s + SPOOL * 64;       // TRI
    u64* remv   = nzb_s + TRI;               // NB
    u64* keep   = remv + NB;                 // NB
    int* slot_s = (int*)(keep + NB);         // TRI

    const int t = threadIdx.x;
    const int warp = t >> 5, lane = t & 31;
    int m = g_cnt; if (m > n) m = n;
    const int mb = (m + 63) >> 6;
    const int tri_lim = tri_start(mb);

    // One-shot parallel preload of the entire working set into smem
    int pc = g_poolcnt; if (pc > SPOOL) pc = SPOOL;
    for (int i = t; i < pc * 64; i += SCAN_THREADS) pool_s[i] = g_pool[i];
    for (int i = t; i < tri_lim; i += SCAN_THREADS) {
        nzb_s[i]  = g_nzb[i];
        slot_s[i] = g_slot[i];
    }
    if (t < NB) { remv[t] = 0ULL; keep[t] = 0ULL; }
    __syncthreads();

    if (warp == 0) {
        for (int b = 0; b < mb; b++) {
            const int tsb  = tri_start(b);
            const int base = tsb - b;            // nzb index of (b, j) is base + j

            // Pre-issue future-column bitmaps (independent of resolve result)
            const int j0 = b + 1 + lane, j1 = j0 + 32, j2 = j1 + 32;
            u64 nzv0 = (j0 < mb) ? nzb_s[base + j0] : 0ULL;
            u64 nzv1 = (j1 < mb) ? nzb_s[base + j1] : 0ULL;
            u64 nzv2 = (j2 < mb) ? nzb_s[base + j2] : 0ULL;

            // Serial resolve (lane 0); remv[b] is final (eager application)
            u64 kept = 0ULL;
            if (lane == 0) {
                u64 supp = remv[b];
                const int vr = m - b * 64;
                const u64 valid = (vr >= 64) ? ~0ULL : ((1ULL << vr) - 1ULL);
                u64 rem = nzb_s[tsb] & ~supp & valid;
                if (rem) {
                    const int ds = slot_s[tsb];
                    const u64* dt = (ds < SPOOL) ? pool_s + ds * 64
                                                 : g_pool + (size_t)ds * 64;
                    while (rem) {
                        const int i = __ffsll((long long)rem) - 1;
                        rem &= rem - 1ULL;
                        if (!((supp >> i) & 1ULL)) {
                            supp |= dt[i];
                            rem  &= ~supp;
                        }
                    }
                }
                kept = ~supp & valid;
                keep[b] = kept;
            }
            kept = __shfl_sync(0xffffffffu, kept, 0);

            // Hit detection across future columns
            unsigned h0 = __ballot_sync(0xffffffffu, (nzv0 & kept) != 0ULL);
            unsigned h1 = __ballot_sync(0xffffffffu, (nzv1 & kept) != 0ULL);
            unsigned h2 = __ballot_sync(0xffffffffu, (nzv2 & kept) != 0ULL);

            // Apply block b's kept rows to each hit column (whole warp per hit)
            #pragma unroll
            for (int g = 0; g < 3; g++) {
                unsigned h = (g == 0) ? h0 : (g == 1) ? h1 : h2;
                const u64 nzv = (g == 0) ? nzv0 : (g == 1) ? nzv1 : nzv2;
                while (h) {
                    const int l = __ffs(h) - 1;
                    h &= h - 1u;
                    const int j = b + 1 + l + 32 * g;
                    u64 nz = __shfl_sync(0xffffffffu, nzv, l) & kept;
                    const int sl = slot_s[base + j];
                    const u64* tl = (sl < SPOOL) ? pool_s + sl * 64
                                                 : g_pool + (size_t)sl * 64;
                    u64 acc = 0ULL;
                    if ((nz >> lane) & 1ULL)        acc |= tl[lane];
                    if ((nz >> (lane + 32)) & 1ULL) acc |= tl[lane + 32];
                    u64 r = redux_or64(acc);
                    if (lane == 0) remv[j] |= r;    // single writer, no atomic
                }
            }
        }
    }
    __syncthreads();

    // Fused finalize: out[i] = s if (s >= 0.6 && kept) else 0
    for (int i = t; i < n; i += SCAN_THREADS) {
        float s = scores[i];
        float v = 0.0f;
        if (s >= 0.6f) {
            int r = g_rank[i];
            if ((keep[r >> 6] >> (r & 63)) & 1ULL) v = s;
        }
        out[i] = v;
    }

    if (t == 0) { g_cnt = 0; g_poolcnt = 0; }   // reset for next graph replay
}

// ---------------------------------------------------------------------------
extern "C" void kernel_launch(void* const* d_in, const int* in_sizes, int n_in,
                              void* d_out, int out_size) {
    const float* boxes  = (const float*)d_in[0];
    const float* scores = (const float*)d_in[1];
    const int n = in_sizes[1];                 // 6000

    cudaFuncSetAttribute(scan_kernel,
                         cudaFuncAttributeMaxDynamicSharedMemorySize, SMEM_BYTES);

    compact_kernel<<<(n + 255) / 256, 256>>>(scores, n);

    rank_kernel<<<(n * 32 + 255) / 256, 256>>>(boxes, n);

    mask_kernel<<<TRI, 64>>>(n);

    scan_kernel<<<1, SCAN_THREADS, SMEM_BYTES>>>(scores, (float*)d_out, n);
}

// round 13
// speedup vs baseline: 1.9854x; 1.9854x over previous
#include <cuda_runtime.h>

#define MAXN 6016
#define NB   94                     // max number of 64-box blocks
#define TRI  (NB * (NB + 1) / 2)    // 4465 upper-triangle tiles
#define SPOOL 320                   // nonzero tiles preloaded into smem
typedef unsigned long long u64;

// Scratch (device globals: allocation is banned; zero-initialized at load)
__device__ float4 g_sboxes[MAXN];
__device__ int    g_rank[MAXN];
__device__ u64    g_plist[MAXN];            // packed (score_bits<<32)|idx
__device__ u64    g_pool[(size_t)TRI * 64]; // nonzero tiles, slot-indexed
__device__ u64    g_nzw[TRI];               // per-slot nonzero-row bitmap
__device__ int    g_meta[TRI];              // per-slot (rb<<16)|cb
__device__ int    g_poolcnt;                // slots used; reset by scan
__device__ int    g_cnt;                    // #prefix boxes; reset by scan

#define SCAN_THREADS 1024
// dynamic smem: pool | nz | kept | und | remk | remu | meta
#define SMEM_BYTES ((SPOOL * 64 + SPOOL + 4 * NB) * 8 + SPOOL * 4)

__device__ __forceinline__ int tri_start(int r) { return r * NB - (r * (r - 1)) / 2; }

__device__ __forceinline__ u64 redux_or64(u64 v) {
    unsigned lo = __reduce_or_sync(0xffffffffu, (unsigned)v);
    unsigned hi = __reduce_or_sync(0xffffffffu, (unsigned)(v >> 32));
    return (u64)lo | ((u64)hi << 32);
}

// ---------------------------------------------------------------------------
// 0) Compact prefix boxes (s >= 0.6) into g_plist.
// ---------------------------------------------------------------------------
__global__ void compact_kernel(const float* __restrict__ scores, int n) {
    int i = blockIdx.x * blockDim.x + threadIdx.x;
    if (i >= n) return;
    float s = scores[i];
    if (s >= 0.6f) {
        int p = atomicAdd(&g_cnt, 1);
        g_plist[p] = ((u64)__float_as_uint(s) << 32) | (unsigned)i;
    }
}

// ---------------------------------------------------------------------------
// 1) Rank within the prefix subset (== global rank for prefix boxes).
// ---------------------------------------------------------------------------
__global__ void rank_kernel(const float* __restrict__ boxes, int n) {
    const int w    = (blockIdx.x * blockDim.x + threadIdx.x) >> 5;
    const int lane = threadIdx.x & 31;
    const int m = g_cnt;
    if (w >= m) return;
    const u64 me = g_plist[w];
    const unsigned sb = (unsigned)(me >> 32);
    const unsigned ib = (unsigned)me;
    int cnt = 0;
    for (int j = lane; j < m; j += 32) {
        u64 e = g_plist[j];
        unsigned sj = (unsigned)(e >> 32);
        unsigned ij = (unsigned)e;
        cnt += (int)((sj > sb) | ((sj == sb) & (ij < ib)));
    }
    #pragma unroll
    for (int o = 16; o; o >>= 1) cnt += __shfl_down_sync(0xffffffffu, cnt, o);
    if (lane == 0) {
        g_sboxes[cnt] = ((const float4*)boxes)[ib];
        g_rank[ib]    = cnt;
    }
}

// ---------------------------------------------------------------------------
// 2) Suppression mask -> slot-indexed pool of NONZERO tiles (+ nz bitmap and
//    (rb,cb) meta per slot). Slot order nondeterministic (atomicAdd) but all
//    reads go through the slot-indexed arrays, so output is deterministic.
// ---------------------------------------------------------------------------
__global__ void mask_kernel(int n) {
    int m = g_cnt; if (m > n) m = n;
    const int mb = (m + 63) >> 6;

    // linear tile -> (rb, cb) with cb >= rb
    const int p = blockIdx.x;
    int rb = (int)((2.0f * NB + 1.0f
                    - sqrtf((2.0f * NB + 1.0f) * (2.0f * NB + 1.0f) - 8.0f * p)) * 0.5f);
    if (rb < 0) rb = 0;
    while (rb + 1 <= NB - 1 && tri_start(rb + 1) <= p) rb++;
    while (rb > 0 && tri_start(rb) > p) rb--;
    const int cb = rb + (p - tri_start(rb));
    if (rb >= mb || cb >= mb) return;

    const int t = threadIdx.x;                   // 0..63
    __shared__ float4   cbox[64];                // {cz, cw, -cx, -cy}
    __shared__ float    carea[64];
    __shared__ unsigned nzhalf[2];
    __shared__ int      slot_sh;
    const int col0 = cb * 64;
    if (col0 + t < m) {
        float4 c = g_sboxes[col0 + t];
        cbox[t]  = make_float4(c.z, c.w, -c.x, -c.y);
        carea[t] = (c.z - c.x) * (c.w - c.y);
    } else {
        cbox[t]  = make_float4(-1e30f, -1e30f, -1e30f, -1e30f);  // -> IoU 0
        carea[t] = 0.f;
    }
    __syncthreads();

    const int row = rb * 64 + t;
    const float4 b   = g_sboxes[row];            // stale if row>=m; bits forced 0
    const float  bz  = b.z,  bw  = b.w;
    const float  nbx = -b.x, nby = -b.y;
    const float  barea = (b.z - b.x) * (b.w - b.y);

    u64 bits = 0ULL;
    #pragma unroll
    for (int k = 0; k < 64; k++) {
        float4 c  = cbox[k];
        float iw  = fmaxf(fminf(bz, c.x) + fminf(nbx, c.z), 0.f);
        float ih  = fmaxf(fminf(bw, c.y) + fminf(nby, c.w), 0.f);
        float inter = iw * ih;
        float uni   = (barea + carea[k]) - inter;
        if (fmaf(-0.5f, uni, inter) > 0.f) bits |= (1ULL << k);
    }
    if (cb == rb) bits &= ((~1ULL) << t);        // keep only cols > row
    if (row >= m) bits = 0ULL;

    unsigned bal = __ballot_sync(0xffffffffu, bits != 0ULL);
    if ((t & 31) == 0) nzhalf[t >> 5] = bal;
    __syncthreads();
    if (t == 0) {
        u64 nzw = (u64)nzhalf[0] | ((u64)nzhalf[1] << 32);
        int s = -1;
        if (nzw != 0ULL) {
            s = atomicAdd(&g_poolcnt, 1);
            g_nzw[s]  = nzw;
            g_meta[s] = (rb << 16) | cb;
        }
        slot_sh = s;
    }
    __syncthreads();
    const int s = slot_sh;
    if (s >= 0) g_pool[(size_t)s * 64 + t] = bits;
}

// ---------------------------------------------------------------------------
// 3) Parallel-fixpoint greedy NMS + finalize. No serial per-block loop.
//    State bitmaps kept/und (38 words). Per round, 32 warps process the ~220
//    nonzero tiles in parallel (all smem):
//      remk[c] |= OR of tile rows whose box is KEPT
//      remu[c] |= OR of tile rows whose box is UNDECIDED
//    then per word: new_kept = und & ~remk & ~remu; new_supp = und & remk;
//    und = und & remu & ~remk. Lowest undecided box always decides ->
//    guaranteed progress; rounds ~ conflict-chain depth (small, sparse data).
//    Result identical to the sequential greedy scan.
// ---------------------------------------------------------------------------
__global__ void scan_kernel(const float* __restrict__ scores,
                            float* __restrict__ out, int n) {
    extern __shared__ u64 dyn[];
    u64* pool_s = dyn;                        // SPOOL*64
    u64* nz_s   = pool_s + SPOOL * 64;        // SPOOL
    u64* kept   = nz_s + SPOOL;               // NB
    u64* und    = kept + NB;                  // NB
    u64* remk   = und + NB;                   // NB
    u64* remu   = remk + NB;                  // NB
    int* meta_s = (int*)(remu + NB);          // SPOOL

    const int t = threadIdx.x;
    const int warp = t >> 5, lane = t & 31;
    int m = g_cnt; if (m > n) m = n;
    const int mb = (m + 63) >> 6;

    // One-shot preload of the sparse working set
    const int pct = g_poolcnt;
    const int pc  = (pct < SPOOL) ? pct : SPOOL;
    for (int i = t; i < pc * 64; i += SCAN_THREADS) pool_s[i] = g_pool[i];
    for (int i = t; i < pc; i += SCAN_THREADS) {
        nz_s[i]   = g_nzw[i];
        meta_s[i] = g_meta[i];
    }
    if (t < NB) {
        kept[t] = 0ULL; remk[t] = 0ULL; remu[t] = 0ULL;
        const int vr = m - t * 64;
        und[t] = (vr >= 64) ? ~0ULL : ((vr > 0) ? ((1ULL << vr) - 1ULL) : 0ULL);
    }
    __syncthreads();

    for (;;) {
        // Phase B: accumulate kept/undecided suppression into remk/remu
        for (int s = warp; s < pc; s += 32) {
            const int md = meta_s[s];
            const int rb = md >> 16, cb = md & 0xffff;
            const u64 kw = kept[rb], uw = und[rb];
            if (nz_s[s] & (kw | uw)) {
                const u64* tl = pool_s + s * 64;
                const u64 r0 = tl[lane], r1 = tl[lane + 32];
                u64 ak = (r0 & (0ULL - ((kw >> lane) & 1ULL)))
                       | (r1 & (0ULL - ((kw >> (lane + 32)) & 1ULL)));
                u64 au = (r0 & (0ULL - ((uw >> lane) & 1ULL)))
                       | (r1 & (0ULL - ((uw >> (lane + 32)) & 1ULL)));
                ak = redux_or64(ak);
                au = redux_or64(au);
                if (lane == 0) {
                    if (ak) atomicOr(&remk[cb], ak);
                    if (au) atomicOr(&remu[cb], au);
                }
            }
        }
        // Overflow tiles (pool didn't fit in smem): correct-but-slow L2 path
        for (int s = SPOOL + warp; s < pct; s += 32) {
            const int md = g_meta[s];
            const int rb = md >> 16, cb = md & 0xffff;
            const u64 kw = kept[rb], uw = und[rb];
            if (g_nzw[s] & (kw | uw)) {
                const u64* tl = g_pool + (size_t)s * 64;
                const u64 r0 = tl[lane], r1 = tl[lane + 32];
                u64 ak = (r0 & (0ULL - ((kw >> lane) & 1ULL)))
                       | (r1 & (0ULL - ((kw >> (lane + 32)) & 1ULL)));
                u64 au = (r0 & (0ULL - ((uw >> lane) & 1ULL)))
                       | (r1 & (0ULL - ((uw >> (lane + 32)) & 1ULL)));
                ak = redux_or64(ak);
                au = redux_or64(au);
                if (lane == 0) {
                    if (ak) atomicOr(&remk[cb], ak);
                    if (au) atomicOr(&remu[cb], au);
                }
            }
        }
        __syncthreads();

        // Phase C: state update + convergence test (+ clear remk/remu)
        int has_und = 0;
        if (t < NB) {
            const u64 u = und[t];
            if (u) {
                const u64 rk = remk[t], ru = remu[t];
                kept[t] |= u & ~rk & ~ru;
                und[t]   = u & ru & ~rk;
            }
            has_und = (und[t] != 0ULL);
            remk[t] = 0ULL;
            remu[t] = 0ULL;
        }
        if (!__syncthreads_or(has_und)) break;
    }

    // Fused finalize: out[i] = s if (s >= 0.6 && kept) else 0
    for (int i = t; i < n; i += SCAN_THREADS) {
        float s = scores[i];
        float v = 0.0f;
        if (s >= 0.6f) {
            int r = g_rank[i];
            if ((kept[r >> 6] >> (r & 63)) & 1ULL) v = s;
        }
        out[i] = v;
    }

    if (t == 0) { g_cnt = 0; g_poolcnt = 0; }   // reset for next graph replay
}

// ---------------------------------------------------------------------------
extern "C" void kernel_launch(void* const* d_in, const int* in_sizes, int n_in,
                              void* d_out, int out_size) {
    const float* boxes  = (const float*)d_in[0];
    const float* scores = (const float*)d_in[1];
    const int n = in_sizes[1];                 // 6000

    cudaFuncSetAttribute(scan_kernel,
                         cudaFuncAttributeMaxDynamicSharedMemorySize, SMEM_BYTES);

    compact_kernel<<<(n + 255) / 256, 256>>>(scores, n);

    rank_kernel<<<(n * 32 + 255) / 256, 256>>>(boxes, n);

    mask_kernel<<<TRI, 64>>>(n);

    scan_kernel<<<1, SCAN_THREADS, SMEM_BYTES>>>(scores, (float*)d_out, n);
}

// round 14
// speedup vs baseline: 2.2320x; 1.1242x over previous
#include <cuda_runtime.h>

#define MAXN 6016
#define NB   94                     // max number of 64-box blocks
#define TRI  (NB * (NB + 1) / 2)    // 4465 upper-triangle tiles
#define SPOOL 320                   // nonzero tiles preloaded into smem
typedef unsigned long long u64;

// Scratch (device globals: allocation is banned; zero-initialized at load)
__device__ float4 g_sboxes[MAXN];
__device__ int    g_rank[MAXN];
__device__ u64    g_plist[MAXN];            // packed (score_bits<<32)|idx
__device__ __align__(16) u64 g_pool[(size_t)TRI * 64]; // nonzero tiles
__device__ u64    g_nzw[TRI];               // per-slot nonzero-row bitmap
__device__ int    g_meta[TRI];              // per-slot (rb<<16)|cb
__device__ int    g_poolcnt;                // slots used; reset by scan
__device__ int    g_cnt;                    // #prefix boxes; reset by scan

#define SCAN_THREADS 1024
// dynamic smem: pool | nz | kept | knew | und | remk | remu | meta
#define SMEM_BYTES ((SPOOL * 64 + SPOOL + 5 * NB) * 8 + SPOOL * 4)

__device__ __forceinline__ int tri_start(int r) { return r * NB - (r * (r - 1)) / 2; }

__device__ __forceinline__ u64 redux_or64(u64 v) {
    unsigned lo = __reduce_or_sync(0xffffffffu, (unsigned)v);
    unsigned hi = __reduce_or_sync(0xffffffffu, (unsigned)(v >> 32));
    return (u64)lo | ((u64)hi << 32);
}

// ---------------------------------------------------------------------------
// 0) Compact prefix boxes (s >= 0.6) into g_plist.
// ---------------------------------------------------------------------------
__global__ void compact_kernel(const float* __restrict__ scores, int n) {
    int i = blockIdx.x * blockDim.x + threadIdx.x;
    if (i >= n) return;
    float s = scores[i];
    if (s >= 0.6f) {
        int p = atomicAdd(&g_cnt, 1);
        g_plist[p] = ((u64)__float_as_uint(s) << 32) | (unsigned)i;
    }
}

// ---------------------------------------------------------------------------
// 1) Rank within the prefix subset (== global rank for prefix boxes).
// ---------------------------------------------------------------------------
__global__ void rank_kernel(const float* __restrict__ boxes, int n) {
    const int w    = (blockIdx.x * blockDim.x + threadIdx.x) >> 5;
    const int lane = threadIdx.x & 31;
    const int m = g_cnt;
    if (w >= m) return;
    const u64 me = g_plist[w];
    const unsigned sb = (unsigned)(me >> 32);
    const unsigned ib = (unsigned)me;
    int cnt = 0;
    for (int j = lane; j < m; j += 32) {
        u64 e = g_plist[j];
        unsigned sj = (unsigned)(e >> 32);
        unsigned ij = (unsigned)e;
        cnt += (int)((sj > sb) | ((sj == sb) & (ij < ib)));
    }
    #pragma unroll
    for (int o = 16; o; o >>= 1) cnt += __shfl_down_sync(0xffffffffu, cnt, o);
    if (lane == 0) {
        g_sboxes[cnt] = ((const float4*)boxes)[ib];
        g_rank[ib]    = cnt;
    }
}

// ---------------------------------------------------------------------------
// 2) Suppression mask -> slot-indexed pool of NONZERO tiles (+ nz bitmap and
//    (rb,cb) meta per slot). Slot order nondeterministic (atomicAdd) but all
//    reads go through the slot-indexed arrays, so output is deterministic.
// ---------------------------------------------------------------------------
__global__ void mask_kernel(int n) {
    int m = g_cnt; if (m > n) m = n;
    const int mb = (m + 63) >> 6;

    // linear tile -> (rb, cb) with cb >= rb
    const int p = blockIdx.x;
    int rb = (int)((2.0f * NB + 1.0f
                    - sqrtf((2.0f * NB + 1.0f) * (2.0f * NB + 1.0f) - 8.0f * p)) * 0.5f);
    if (rb < 0) rb = 0;
    while (rb + 1 <= NB - 1 && tri_start(rb + 1) <= p) rb++;
    while (rb > 0 && tri_start(rb) > p) rb--;
    const int cb = rb + (p - tri_start(rb));
    if (rb >= mb || cb >= mb) return;

    const int t = threadIdx.x;                   // 0..63
    __shared__ float4   cbox[64];                // {cz, cw, -cx, -cy}
    __shared__ float    carea[64];
    __shared__ unsigned nzhalf[2];
    __shared__ int      slot_sh;
    const int col0 = cb * 64;
    if (col0 + t < m) {
        float4 c = g_sboxes[col0 + t];
        cbox[t]  = make_float4(c.z, c.w, -c.x, -c.y);
        carea[t] = (c.z - c.x) * (c.w - c.y);
    } else {
        cbox[t]  = make_float4(-1e30f, -1e30f, -1e30f, -1e30f);  // -> IoU 0
        carea[t] = 0.f;
    }
    __syncthreads();

    const int row = rb * 64 + t;
    const float4 b   = g_sboxes[row];            // stale if row>=m; bits forced 0
    const float  bz  = b.z,  bw  = b.w;
    const float  nbx = -b.x, nby = -b.y;
    const float  barea = (b.z - b.x) * (b.w - b.y);

    u64 bits = 0ULL;
    #pragma unroll
    for (int k = 0; k < 64; k++) {
        float4 c  = cbox[k];
        float iw  = fmaxf(fminf(bz, c.x) + fminf(nbx, c.z), 0.f);
        float ih  = fmaxf(fminf(bw, c.y) + fminf(nby, c.w), 0.f);
        float inter = iw * ih;
        float uni   = (barea + carea[k]) - inter;
        if (fmaf(-0.5f, uni, inter) > 0.f) bits |= (1ULL << k);
    }
    if (cb == rb) bits &= ((~1ULL) << t);        // keep only cols > row
    if (row >= m) bits = 0ULL;

    unsigned bal = __ballot_sync(0xffffffffu, bits != 0ULL);
    if ((t & 31) == 0) nzhalf[t >> 5] = bal;
    __syncthreads();
    if (t == 0) {
        u64 nzw = (u64)nzhalf[0] | ((u64)nzhalf[1] << 32);
        int s = -1;
        if (nzw != 0ULL) {
            s = atomicAdd(&g_poolcnt, 1);
            g_nzw[s]  = nzw;
            g_meta[s] = (rb << 16) | cb;
        }
        slot_sh = s;
    }
    __syncthreads();
    const int s = slot_sh;
    if (s >= 0) g_pool[(size_t)s * 64 + t] = bits;
}

// ---------------------------------------------------------------------------
// 3) INCREMENTAL parallel-fixpoint greedy NMS + finalize.
//    remk (kept-predecessor mask) is persistent: each kept box's suppression
//    is applied exactly once, in the round after it is decided, via the
//    knew bitmap. remu (undecided-predecessor mask) is rebuilt per round
//    from the shrinking und set. Per round a tile is touched only if it has
//    newly-kept or undecided rows -> total work ~ O(nonzero tiles) + chains.
//    Decisions per round are identical to the full-recompute fixpoint, which
//    reproduces the sequential greedy scan exactly.
// ---------------------------------------------------------------------------
__global__ void scan_kernel(const float* __restrict__ scores,
                            float* __restrict__ out, int n) {
    extern __shared__ u64 dyn[];
    u64* pool_s = dyn;                        // SPOOL*64
    u64* nz_s   = pool_s + SPOOL * 64;        // SPOOL
    u64* kept   = nz_s + SPOOL;               // NB
    u64* knew   = kept + NB;                  // NB (boxes kept last round)
    u64* und    = knew + NB;                  // NB
    u64* remk   = und + NB;                   // NB (persistent)
    u64* remu   = remk + NB;                  // NB (per-round)
    int* meta_s = (int*)(remu + NB);          // SPOOL

    const int t = threadIdx.x;
    const int warp = t >> 5, lane = t & 31;
    int m = g_cnt; if (m > n) m = n;
    const int mb = (m + 63) >> 6;

    // One-shot preload (16B vectorized: slot stride 512B keeps alignment)
    const int pct = g_poolcnt;
    const int pc  = (pct < SPOOL) ? pct : SPOOL;
    {
        const ulonglong2* src = (const ulonglong2*)g_pool;
        ulonglong2*       dst = (ulonglong2*)pool_s;
        for (int i = t; i < pc * 32; i += SCAN_THREADS) dst[i] = src[i];
    }
    for (int i = t; i < pc; i += SCAN_THREADS) {
        nz_s[i]   = g_nzw[i];
        meta_s[i] = g_meta[i];
    }
    if (t < NB) {
        kept[t] = 0ULL; knew[t] = 0ULL; remk[t] = 0ULL; remu[t] = 0ULL;
        const int vr = m - t * 64;
        und[t] = (vr >= 64) ? ~0ULL : ((vr > 0) ? ((1ULL << vr) - 1ULL) : 0ULL);
    }
    __syncthreads();

    for (;;) {
        // Phase B: apply newly-kept rows (once, into persistent remk) and
        // undecided rows (into per-round remu)
        for (int s = warp; s < pc; s += 32) {
            const int md = meta_s[s];
            const int rb = md >> 16, cb = md & 0xffff;
            const u64 kn = knew[rb], uw = und[rb];
            if (nz_s[s] & (kn | uw)) {
                const u64* tl = pool_s + s * 64;
                const u64 r0 = tl[lane], r1 = tl[lane + 32];
                u64 ak = (r0 & (0ULL - ((kn >> lane) & 1ULL)))
                       | (r1 & (0ULL - ((kn >> (lane + 32)) & 1ULL)));
                u64 au = (r0 & (0ULL - ((uw >> lane) & 1ULL)))
                       | (r1 & (0ULL - ((uw >> (lane + 32)) & 1ULL)));
                ak = redux_or64(ak);
                au = redux_or64(au);
                if (lane == 0) {
                    if (ak) atomicOr(&remk[cb], ak);
                    if (au) atomicOr(&remu[cb], au);
                }
            }
        }
        // Overflow tiles (pool didn't fit in smem): correct-but-slow L2 path
        for (int s = SPOOL + warp; s < pct; s += 32) {
            const int md = g_meta[s];
            const int rb = md >> 16, cb = md & 0xffff;
            const u64 kn = knew[rb], uw = und[rb];
            if (g_nzw[s] & (kn | uw)) {
                const u64* tl = g_pool + (size_t)s * 64;
                const u64 r0 = tl[lane], r1 = tl[lane + 32];
                u64 ak = (r0 & (0ULL - ((kn >> lane) & 1ULL)))
                       | (r1 & (0ULL - ((kn >> (lane + 32)) & 1ULL)));
                u64 au = (r0 & (0ULL - ((uw >> lane) & 1ULL)))
                       | (r1 & (0ULL - ((uw >> (lane + 32)) & 1ULL)));
                ak = redux_or64(ak);
                au = redux_or64(au);
                if (lane == 0) {
                    if (ak) atomicOr(&remk[cb], ak);
                    if (au) atomicOr(&remu[cb], au);
                }
            }
        }
        __syncthreads();

        // Phase C: decide; remk persists, remu cleared for next round
        int has_und = 0;
        if (t < NB) {
            const u64 u = und[t];
            u64 kn = 0ULL;
            if (u) {
                const u64 rk = remk[t], ru = remu[t];
                kn = u & ~rk & ~ru;            // no kept & no undecided preds
                kept[t] |= kn;
                und[t]   = u & ru & ~rk;       // suppressed (rk) boxes drop out
            }
            knew[t] = kn;
            has_und = (und[t] != 0ULL);
            remu[t] = 0ULL;
        }
        if (!__syncthreads_or(has_und)) break;
    }

    // Fused finalize: out[i] = s if (s >= 0.6 && kept) else 0
    for (int i = t; i < n; i += SCAN_THREADS) {
        float s = scores[i];
        float v = 0.0f;
        if (s >= 0.6f) {
            int r = g_rank[i];
            if ((kept[r >> 6] >> (r & 63)) & 1ULL) v = s;
        }
        out[i] = v;
    }

    if (t == 0) { g_cnt = 0; g_poolcnt = 0; }   // reset for next graph replay
}

// ---------------------------------------------------------------------------
extern "C" void kernel_launch(void* const* d_in, const int* in_sizes, int n_in,
                              void* d_out, int out_size) {
    const float* boxes  = (const float*)d_in[0];
    const float* scores = (const float*)d_in[1];
    const int n = in_sizes[1];                 // 6000

    cudaFuncSetAttribute(scan_kernel,
                         cudaFuncAttributeMaxDynamicSharedMemorySize, SMEM_BYTES);

    compact_kernel<<<(n + 255) / 256, 256>>>(scores, n);

    rank_kernel<<<(n * 32 + 255) / 256, 256>>>(boxes, n);

    mask_kernel<<<TRI, 64>>>(n);

    scan_kernel<<<1, SCAN_THREADS, SMEM_BYTES>>>(scores, (float*)d_out, n);
}

// round 15
// speedup vs baseline: 2.5456x; 1.1405x over previous
#include <cuda_runtime.h>

#define MAXN 6016
#define NB   94                     // max number of 64-box blocks
#define TRI  (NB * (NB + 1) / 2)    // 4465 upper-triangle tiles
#define SPOOL 320                   // nonzero tiles preloaded into smem
typedef unsigned long long u64;

// Scratch (device globals: allocation is banned; zero-initialized at load)
__device__ float4 g_sboxes[MAXN];
__device__ int    g_rank[MAXN];
__device__ u64    g_plist[MAXN];            // packed (score_bits<<32)|idx
__device__ __align__(16) u64 g_pool[(size_t)TRI * 64]; // nonzero tiles
__device__ u64    g_nzw[TRI];               // per-slot nonzero-row bitmap
__device__ u64    g_colOR[TRI];             // per-slot OR of all rows
__device__ int    g_meta[TRI];              // per-slot (rb<<16)|cb
__device__ int    g_poolcnt;                // slots used; reset by scan
__device__ int    g_cnt;                    // #prefix boxes; reset by scan

#define SCAN_THREADS 1024
// dynamic smem: pool | nz | kept | knew | und | remk | remu | meta | wl | wl_cnt
#define SMEM_BYTES ((SPOOL * 64 + SPOOL + 5 * NB) * 8 + 2 * SPOOL * 4 + 16)

__device__ __forceinline__ int tri_start(int r) { return r * NB - (r * (r - 1)) / 2; }

__device__ __forceinline__ unsigned smem_u32(const void* p) {
    return (unsigned)__cvta_generic_to_shared(p);
}
__device__ __forceinline__ void cp_async16(unsigned dst, const void* src) {
    asm volatile("cp.async.cg.shared.global [%0], [%1], 16;" :: "r"(dst), "l"(src));
}
#define CP_COMMIT() asm volatile("cp.async.commit_group;" ::: "memory")
#define CP_WAIT0()  asm volatile("cp.async.wait_group 0;" ::: "memory")

__device__ __forceinline__ u64 redux_or64(u64 v) {
    unsigned lo = __reduce_or_sync(0xffffffffu, (unsigned)v);
    unsigned hi = __reduce_or_sync(0xffffffffu, (unsigned)(v >> 32));
    return (u64)lo | ((u64)hi << 32);
}

// ---------------------------------------------------------------------------
// 0) Compact prefix boxes (s >= 0.6) into g_plist.
// ---------------------------------------------------------------------------
__global__ void compact_kernel(const float* __restrict__ scores, int n) {
    int i = blockIdx.x * blockDim.x + threadIdx.x;
    if (i >= n) return;
    float s = scores[i];
    if (s >= 0.6f) {
        int p = atomicAdd(&g_cnt, 1);
        g_plist[p] = ((u64)__float_as_uint(s) << 32) | (unsigned)i;
    }
}

// ---------------------------------------------------------------------------
// 1) Rank within the prefix subset (== global rank for prefix boxes).
// ---------------------------------------------------------------------------
__global__ void rank_kernel(const float* __restrict__ boxes, int n) {
    const int w    = (blockIdx.x * blockDim.x + threadIdx.x) >> 5;
    const int lane = threadIdx.x & 31;
    const int m = g_cnt;
    if (w >= m) return;
    const u64 me = g_plist[w];
    const unsigned sb = (unsigned)(me >> 32);
    const unsigned ib = (unsigned)me;
    int cnt = 0;
    for (int j = lane; j < m; j += 32) {
        u64 e = g_plist[j];
        unsigned sj = (unsigned)(e >> 32);
        unsigned ij = (unsigned)e;
        cnt += (int)((sj > sb) | ((sj == sb) & (ij < ib)));
    }
    #pragma unroll
    for (int o = 16; o; o >>= 1) cnt += __shfl_down_sync(0xffffffffu, cnt, o);
    if (lane == 0) {
        g_sboxes[cnt] = ((const float4*)boxes)[ib];
        g_rank[ib]    = cnt;
    }
}

// ---------------------------------------------------------------------------
// 2) Suppression mask -> slot-indexed pool of NONZERO tiles, with per-slot
//    nonzero-row bitmap, full column-OR (for fixpoint round 1), and (rb,cb).
//    Slot order nondeterministic (atomicAdd) but all reads go through the
//    slot-indexed arrays, so output is deterministic.
// ---------------------------------------------------------------------------
__global__ void mask_kernel(int n) {
    int m = g_cnt; if (m > n) m = n;
    const int mb = (m + 63) >> 6;

    // linear tile -> (rb, cb) with cb >= rb
    const int p = blockIdx.x;
    int rb = (int)((2.0f * NB + 1.0f
                    - sqrtf((2.0f * NB + 1.0f) * (2.0f * NB + 1.0f) - 8.0f * p)) * 0.5f);
    if (rb < 0) rb = 0;
    while (rb + 1 <= NB - 1 && tri_start(rb + 1) <= p) rb++;
    while (rb > 0 && tri_start(rb) > p) rb--;
    const int cb = rb + (p - tri_start(rb));
    if (rb >= mb || cb >= mb) return;

    const int t = threadIdx.x;                   // 0..63
    __shared__ float4   cbox[64];                // {cz, cw, -cx, -cy}
    __shared__ float    carea[64];
    __shared__ unsigned nzhalf[2];
    __shared__ u64      corhalf[2];
    __shared__ int      slot_sh;
    const int col0 = cb * 64;
    if (col0 + t < m) {
        float4 c = g_sboxes[col0 + t];
        cbox[t]  = make_float4(c.z, c.w, -c.x, -c.y);
        carea[t] = (c.z - c.x) * (c.w - c.y);
    } else {
        cbox[t]  = make_float4(-1e30f, -1e30f, -1e30f, -1e30f);  // -> IoU 0
        carea[t] = 0.f;
    }
    __syncthreads();

    const int row = rb * 64 + t;
    const float4 b   = g_sboxes[row];            // stale if row>=m; bits forced 0
    const float  bz  = b.z,  bw  = b.w;
    const float  nbx = -b.x, nby = -b.y;
    const float  barea = (b.z - b.x) * (b.w - b.y);

    u64 bits = 0ULL;
    #pragma unroll
    for (int k = 0; k < 64; k++) {
        float4 c  = cbox[k];
        float iw  = fmaxf(fminf(bz, c.x) + fminf(nbx, c.z), 0.f);
        float ih  = fmaxf(fminf(bw, c.y) + fminf(nby, c.w), 0.f);
        float inter = iw * ih;
        float uni   = (barea + carea[k]) - inter;
        if (fmaf(-0.5f, uni, inter) > 0.f) bits |= (1ULL << k);
    }
    if (cb == rb) bits &= ((~1ULL) << t);        // keep only cols > row
    if (row >= m) bits = 0ULL;

    unsigned bal = __ballot_sync(0xffffffffu, bits != 0ULL);
    u64 cor = redux_or64(bits);
    if ((t & 31) == 0) { nzhalf[t >> 5] = bal; corhalf[t >> 5] = cor; }
    __syncthreads();
    if (t == 0) {
        u64 nzw = (u64)nzhalf[0] | ((u64)nzhalf[1] << 32);
        int s = -1;
        if (nzw != 0ULL) {
            s = atomicAdd(&g_poolcnt, 1);
            g_nzw[s]   = nzw;
            g_colOR[s] = corhalf[0] | corhalf[1];
            g_meta[s]  = (rb << 16) | cb;
        }
        slot_sh = s;
    }
    __syncthreads();
    const int s = slot_sh;
    if (s >= 0) g_pool[(size_t)s * 64 + t] = bits;
}

// ---------------------------------------------------------------------------
// 3) Incremental parallel-fixpoint greedy NMS + finalize, WORKLIST form.
//    Round 1 uses precomputed column-ORs (no tile data) and overlaps the
//    cp.async preload of the tile pool. Rounds 2+: a one-tile-per-THREAD
//    check phase compacts active slots (nz & (knew|und) on their row-block)
//    into a worklist; full warps then process only those. remk persists
//    (each kept box applied exactly once); remu rebuilt per round.
//    Decisions identical to the sequential greedy scan.
// ---------------------------------------------------------------------------
__global__ void scan_kernel(const float* __restrict__ scores,
                            float* __restrict__ out, int n) {
    extern __shared__ __align__(16) u64 dyn[];
    u64* pool_s = dyn;                        // SPOOL*64
    u64* nz_s   = pool_s + SPOOL * 64;        // SPOOL
    u64* kept   = nz_s + SPOOL;               // NB
    u64* knew   = kept + NB;                  // NB
    u64* und    = knew + NB;                  // NB
    u64* remk   = und + NB;                   // NB (persistent)
    u64* remu   = remk + NB;                  // NB (per-round)
    int* meta_s = (int*)(remu + NB);          // SPOOL
    int* wl     = meta_s + SPOOL;             // SPOOL
    int* wl_cnt = wl + SPOOL;                 // 1

    const int t = threadIdx.x;
    const int warp = t >> 5, lane = t & 31;
    int m = g_cnt; if (m > n) m = n;
    const int mb = (m + 63) >> 6;

    const int pct = g_poolcnt;
    const int pc  = (pct < SPOOL) ? pct : SPOOL;

    // Async pool preload (consumed from round 2 on; overlaps round 1)
    {
        const ulonglong2* src = (const ulonglong2*)g_pool;
        ulonglong2*       dst = (ulonglong2*)pool_s;
        for (int i = t; i < pc * 32; i += SCAN_THREADS)
            cp_async16(smem_u32(dst + i), src + i);
        CP_COMMIT();
    }
    for (int i = t; i < pc; i += SCAN_THREADS) {
        nz_s[i]   = g_nzw[i];
        meta_s[i] = g_meta[i];
    }
    if (t < NB) {
        kept[t] = 0ULL; knew[t] = 0ULL; remk[t] = 0ULL; remu[t] = 0ULL;
        const int vr = m - t * 64;
        und[t] = (vr >= 64) ? ~0ULL : ((vr > 0) ? ((1ULL << vr) - 1ULL) : 0ULL);
    }
    if (t == 0) *wl_cnt = 0;
    __syncthreads();

    // ---- Round 1: und = all valid -> remu via precomputed column-ORs ----
    for (int i = t; i < pct; i += SCAN_THREADS) {
        const int md = (i < SPOOL) ? meta_s[i] : g_meta[i];
        atomicOr(&remu[md & 0xffff], g_colOR[i]);
    }
    __syncthreads();
    int has_und = 0;
    if (t < NB) {
        const u64 u = und[t];
        u64 kn = 0ULL;
        if (u) {
            const u64 ru = remu[t];
            kn = u & ~ru;                      // remk is 0 in round 1
            kept[t] |= kn;
            und[t]   = u & ru;
        }
        knew[t] = kn;
        has_und = (und[t] != 0ULL);
        remu[t] = 0ULL;
    }
    const int live = __syncthreads_or(has_und);
    CP_WAIT0();                                // own cp.async groups done
    __syncthreads();                           // pool_s visible to all

    if (live) {
        for (;;) {
            // Phase A: parallel per-thread check -> worklist of active slots
            for (int i = t; i < pc; i += SCAN_THREADS) {
                const int rb = meta_s[i] >> 16;
                if (nz_s[i] & (knew[rb] | und[rb]))
                    wl[atomicAdd(wl_cnt, 1)] = i;
            }
            __syncthreads();

            // Phase B: full-warp processing of active tiles (smem-resident)
            const int wc = *wl_cnt;
            for (int i = warp; i < wc; i += 32) {
                const int s  = wl[i];
                const int md = meta_s[s];
                const int rb = md >> 16, cb = md & 0xffff;
                const u64 kn = knew[rb], uw = und[rb];
                const u64* tl = pool_s + s * 64;
                const u64 r0 = tl[lane], r1 = tl[lane + 32];
                u64 ak = (r0 & (0ULL - ((kn >> lane) & 1ULL)))
                       | (r1 & (0ULL - ((kn >> (lane + 32)) & 1ULL)));
                u64 au = (r0 & (0ULL - ((uw >> lane) & 1ULL)))
                       | (r1 & (0ULL - ((uw >> (lane + 32)) & 1ULL)));
                ak = redux_or64(ak);
                au = redux_or64(au);
                if (lane == 0) {
                    if (ak) atomicOr(&remk[cb], ak);
                    if (au) atomicOr(&remu[cb], au);
                }
            }
            // Overflow slots (pool didn't fit in smem): correct-but-slow path
            for (int s = SPOOL + warp; s < pct; s += 32) {
                const int md = g_meta[s];
                const int rb = md >> 16, cb = md & 0xffff;
                const u64 kn = knew[rb], uw = und[rb];
                if (g_nzw[s] & (kn | uw)) {
                    const u64* tl = g_pool + (size_t)s * 64;
                    const u64 r0 = tl[lane], r1 = tl[lane + 32];
                    u64 ak = (r0 & (0ULL - ((kn >> lane) & 1ULL)))
                           | (r1 & (0ULL - ((kn >> (lane + 32)) & 1ULL)));
                    u64 au = (r0 & (0ULL - ((uw >> lane) & 1ULL)))
                           | (r1 & (0ULL - ((uw >> (lane + 32)) & 1ULL)));
                    ak = redux_or64(ak);
                    au = redux_or64(au);
                    if (lane == 0) {
                        if (ak) atomicOr(&remk[cb], ak);
                        if (au) atomicOr(&remu[cb], au);
                    }
                }
            }
            __syncthreads();

            // Phase C: decide; remk persists, remu/worklist cleared
            int hu = 0;
            if (t < NB) {
                const u64 u = und[t];
                u64 kn = 0ULL;
                if (u) {
                    const u64 rk = remk[t], ru = remu[t];
                    kn = u & ~rk & ~ru;
                    kept[t] |= kn;
                    und[t]   = u & ru & ~rk;
                }
                knew[t] = kn;
                hu = (und[t] != 0ULL);
                remu[t] = 0ULL;
            }
            if (t == 0) *wl_cnt = 0;
            if (!__syncthreads_or(hu)) break;
        }
    }

    // Fused finalize: out[i] = s if (s >= 0.6 && kept) else 0
    for (int i = t; i < n; i += SCAN_THREADS) {
        float s = scores[i];
        float v = 0.0f;
        if (s >= 0.6f) {
            int r = g_rank[i];
            if ((kept[r >> 6] >> (r & 63)) & 1ULL) v = s;
        }
        out[i] = v;
    }

    if (t == 0) { g_cnt = 0; g_poolcnt = 0; }   // reset for next graph replay
}

// ---------------------------------------------------------------------------
extern "C" void kernel_launch(void* const* d_in, const int* in_sizes, int n_in,
                              void* d_out, int out_size) {
    const float* boxes  = (const float*)d_in[0];
    const float* scores = (const float*)d_in[1];
    const int n = in_sizes[1];                 // 6000

    cudaFuncSetAttribute(scan_kernel,
                         cudaFuncAttributeMaxDynamicSharedMemorySize, SMEM_BYTES);

    compact_kernel<<<(n + 255) / 256, 256>>>(scores, n);

    rank_kernel<<<(n * 32 + 255) / 256, 256>>>(boxes, n);

    mask_kernel<<<TRI, 64>>>(n);

    scan_kernel<<<1, SCAN_THREADS, SMEM_BYTES>>>(scores, (float*)d_out, n);
}